// round 3
// baseline (speedup 1.0000x reference)
#include <cuda_runtime.h>
#include <cstdint>
#include <cstddef>

// Net_quantize: fused MFL recurrence + LSQ fake-quant + 2 quantized linear layers.
// One thread per row; x read directly (each 32-col chunk of a row = one 128B line,
// 100% sector utilization). fc1/fc2 via DP4A on exact int8 levels.
//
// Inputs: x(M*128), mfl_alpha, mfl_beta, a1, a2, a3, W1(16*128), b1(16), wa1,
//         W2(10*16), b2(10), wa2.  Output: out(M*10) fp32.

#define THREADS 256
#define NCOLS   128

__global__ __launch_bounds__(THREADS, 4)
void net_quant_kernel(const float* __restrict__ x,
                      const float* __restrict__ p_alpha,
                      const float* __restrict__ p_beta,
                      const float* __restrict__ p_a1,
                      const float* __restrict__ p_a2,
                      const float* __restrict__ p_a3,
                      const float* __restrict__ W1,
                      const float* __restrict__ b1,
                      const float* __restrict__ p_wa1,
                      const float* __restrict__ W2,
                      const float* __restrict__ b2,
                      const float* __restrict__ p_wa2,
                      float* __restrict__ out)
{
    __shared__ int   w1p[32 * 16];        // [kc][j], kc = k/4, bytes = cols 4kc..4kc+3
    __shared__ int   w2p[10 * 4];         // [j][c]
    __shared__ float outs[THREADS * 10];  // coalesced output staging

    const int tid = threadIdx.x;
    const size_t row = (size_t)blockIdx.x * THREADS + tid;

    const float alpha = p_alpha[0];
    const float beta  = p_beta[0];
    const float a1  = p_a1[0];
    const float a2  = p_a2[0];
    const float a3  = p_a3[0];
    const float wa1 = p_wa1[0];
    const float wa2 = p_wa2[0];
    const float inv_a1  = 1.0f / a1;
    const float inv_a2  = 1.0f / a2;
    const float inv_a3  = 1.0f / a3;
    const float inv_wa1 = 1.0f / wa1;
    const float inv_wa2 = 1.0f / wa2;

    // ---- quantize + pack W1 (16x128) into smem, layout [kc][j] ----
    for (int i = tid; i < 512; i += THREADS) {
        const int kc = i >> 4, j = i & 15;
        unsigned v = 0;
#pragma unroll
        for (int b = 0; b < 4; ++b) {
            float t = W1[j * 128 + kc * 4 + b] * inv_wa1;
            t = fminf(fmaxf(t, -128.0f), 127.0f);
            const int q = __float2int_rn(t);
            v |= ((unsigned)(q & 0xff)) << (8 * b);
        }
        w1p[i] = (int)v;
    }
    // ---- quantize + pack W2 (10x16) ----
    if (tid < 40) {
        const int j = tid >> 2, c = tid & 3;
        unsigned v = 0;
#pragma unroll
        for (int b = 0; b < 4; ++b) {
            float t = W2[j * 16 + c * 4 + b] * inv_wa2;
            t = fminf(fmaxf(t, -128.0f), 127.0f);
            const int q = __float2int_rn(t);
            v |= ((unsigned)(q & 0xff)) << (8 * b);
        }
        w2p[tid] = (int)v;
    }
    __syncthreads();

    // ---- MFL recurrence + fc1 (int8 dp4a accumulation) ----
    const float4* x4 = reinterpret_cast<const float4*>(x + row * NCOLS);

    float w = 1.0f;
    int acc[16];
#pragma unroll
    for (int j = 0; j < 16; ++j) acc[j] = 0;
    unsigned hp = 0;

    float4 cur = x4[0];                       // first line of the row

#pragma unroll
    for (int chunk = 0; chunk < 4; ++chunk) {
        // prefetch first float4 of the NEXT chunk -> pulls that 128B line into L1
        const float4 nxt = x4[chunk < 3 ? (chunk + 1) * 8 : 31];

#pragma unroll
        for (int g = 0; g < 8; ++g) {
            const float4 v = (g == 0) ? cur : x4[chunk * 8 + g];   // L1 hit
            const float xe[4] = {v.x, v.y, v.z, v.w};

#pragma unroll
            for (int b = 0; b < 4; ++b) {
                // quantize w_k (clip+round-half-even == cvt.rni.sat.s8)
                const float t = w * inv_a1;
                int hq;
                asm("cvt.rni.sat.s8.f32 %0, %1;" : "=r"(hq) : "f"(t));
                hp = __byte_perm(hp, (unsigned)hq, 0x4321);

                // recurrence: w' = alpha*rcp(w) + (w - beta*x_k)
                // chain: rcp(16) -> fma(4); the t2 fma overlaps the MUFU.
                const float t2 = __fmaf_rn(-beta, xe[b], w);
                float r;
                asm("rcp.approx.f32 %0, %1;" : "=f"(r) : "f"(w));
                w = __fmaf_rn(alpha, r, t2);
            }

            // dp4a group for 4 packed columns
            const int kc = chunk * 8 + g;
            const int4* wp = reinterpret_cast<const int4*>(&w1p[kc * 16]);
            const int4 w0 = wp[0], w1v = wp[1], w2v = wp[2], w3v = wp[3];
            acc[0]  = __dp4a((int)hp, w0.x,  acc[0]);
            acc[1]  = __dp4a((int)hp, w0.y,  acc[1]);
            acc[2]  = __dp4a((int)hp, w0.z,  acc[2]);
            acc[3]  = __dp4a((int)hp, w0.w,  acc[3]);
            acc[4]  = __dp4a((int)hp, w1v.x, acc[4]);
            acc[5]  = __dp4a((int)hp, w1v.y, acc[5]);
            acc[6]  = __dp4a((int)hp, w1v.z, acc[6]);
            acc[7]  = __dp4a((int)hp, w1v.w, acc[7]);
            acc[8]  = __dp4a((int)hp, w2v.x, acc[8]);
            acc[9]  = __dp4a((int)hp, w2v.y, acc[9]);
            acc[10] = __dp4a((int)hp, w2v.z, acc[10]);
            acc[11] = __dp4a((int)hp, w2v.w, acc[11]);
            acc[12] = __dp4a((int)hp, w3v.x, acc[12]);
            acc[13] = __dp4a((int)hp, w3v.y, acc[13]);
            acc[14] = __dp4a((int)hp, w3v.z, acc[14]);
            acc[15] = __dp4a((int)hp, w3v.w, acc[15]);
        }
        cur = nxt;
    }

    // ---- epilogue: bias, sigmoid, unsigned quant, signed quant, fc2 (dp4a) ----
    const float s1scale = a1 * wa1;
    unsigned sp[4];
    unsigned spacc = 0;
#pragma unroll
    for (int j = 0; j < 16; ++j) {
        const float h = __fmaf_rn((float)acc[j], s1scale, b1[j]);
        const float sg = __fdividef(1.0f, 1.0f + __expf(-h));
        float u = sg * inv_a2;
        u = fminf(fmaxf(u, 0.0f), 255.0f);
        const float s = (float)__float2int_rn(u) * a2;          // post-sigmoid fq
        float v2 = s * inv_a3;
        int s2q;
        asm("cvt.rni.sat.s8.f32 %0, %1;" : "=r"(s2q) : "f"(v2)); // qAct3 level
        spacc = __byte_perm(spacc, (unsigned)s2q, 0x4321);
        if ((j & 3) == 3) sp[j >> 2] = spacc;
    }

    const float s2scale = a3 * wa2;
#pragma unroll
    for (int j = 0; j < 10; ++j) {
        int o = 0;
        o = __dp4a((int)sp[0], w2p[j * 4 + 0], o);
        o = __dp4a((int)sp[1], w2p[j * 4 + 1], o);
        o = __dp4a((int)sp[2], w2p[j * 4 + 2], o);
        o = __dp4a((int)sp[3], w2p[j * 4 + 3], o);
        outs[tid * 10 + j] = __fmaf_rn((float)o, s2scale, b2[j]);
    }
    __syncthreads();

    // coalesced output store: 2560 contiguous floats per block
    const size_t obase = (size_t)blockIdx.x * THREADS * 10;
#pragma unroll
    for (int t = 0; t < 10; ++t) {
        const int i = t * THREADS + tid;
        out[obase + i] = outs[i];
    }
}

extern "C" void kernel_launch(void* const* d_in, const int* in_sizes, int n_in,
                              void* d_out, int out_size)
{
    const float* x       = (const float*)d_in[0];
    const float* p_alpha = (const float*)d_in[1];
    const float* p_beta  = (const float*)d_in[2];
    const float* p_a1    = (const float*)d_in[3];
    const float* p_a2    = (const float*)d_in[4];
    const float* p_a3    = (const float*)d_in[5];
    const float* W1      = (const float*)d_in[6];
    const float* b1      = (const float*)d_in[7];
    const float* p_wa1   = (const float*)d_in[8];
    const float* W2      = (const float*)d_in[9];
    const float* b2      = (const float*)d_in[10];
    const float* p_wa2   = (const float*)d_in[11];
    float* out = (float*)d_out;

    const int M = in_sizes[0] / NCOLS;     // 262144
    const int blocks = M / THREADS;        // 1024

    net_quant_kernel<<<blocks, THREADS>>>(x, p_alpha, p_beta, p_a1, p_a2, p_a3,
                                          W1, b1, p_wa1, W2, b2, p_wa2, out);
}

// round 4
// speedup vs baseline: 1.2081x; 1.2081x over previous
#include <cuda_runtime.h>
#include <cstdint>
#include <cstddef>

// Net_quantize: fused MFL recurrence + LSQ fake-quant + 2 quantized linear layers.
// One thread per row. x staged through SMEM in 256x16 chunks with a 2-deep
// software pipeline (register prefetch of chunk c+1 issued before the barrier,
// so DRAM latency hides under chunk-c compute). fc1/fc2 via DP4A on exact int8
// quantization levels.

#define THREADS 256
#define NCOLS   128
#define CCOLS   16            // columns per chunk
#define NCHUNK  8
#define XPAD    17            // odd stride -> conflict-free scalar LDS
#define BUFSZ   (THREADS * XPAD)

__global__ __launch_bounds__(THREADS, 4)
void net_quant_kernel(const float* __restrict__ x,
                      const float* __restrict__ p_alpha,
                      const float* __restrict__ p_beta,
                      const float* __restrict__ p_a1,
                      const float* __restrict__ p_a2,
                      const float* __restrict__ p_a3,
                      const float* __restrict__ W1,
                      const float* __restrict__ b1,
                      const float* __restrict__ p_wa1,
                      const float* __restrict__ W2,
                      const float* __restrict__ b2,
                      const float* __restrict__ p_wa2,
                      float* __restrict__ out)
{
    __shared__ float xs[2 * BUFSZ];       // 34816 B, double-buffered staging
    __shared__ int   w1p[32 * 16];        // [kc][j], kc = k/4
    __shared__ int   w2p[10 * 4];         // [j][c]

    const int tid  = threadIdx.x;
    const int row0 = blockIdx.x * THREADS;

    const float alpha = p_alpha[0];
    const float beta  = p_beta[0];
    const float a1  = p_a1[0];
    const float a2  = p_a2[0];
    const float a3  = p_a3[0];
    const float wa1 = p_wa1[0];
    const float wa2 = p_wa2[0];
    const float inv_a1  = 1.0f / a1;
    const float inv_a2  = 1.0f / a2;
    const float inv_a3  = 1.0f / a3;
    const float inv_wa1 = 1.0f / wa1;
    const float inv_wa2 = 1.0f / wa2;

    // ---- quantize + pack W1 (16x128) into smem, layout [kc][j] ----
    for (int i = tid; i < 512; i += THREADS) {
        const int kc = i >> 4, j = i & 15;
        unsigned v = 0;
#pragma unroll
        for (int b = 0; b < 4; ++b) {
            float t = W1[j * 128 + kc * 4 + b] * inv_wa1;
            int q;
            asm("cvt.rni.sat.s8.f32 %0, %1;" : "=r"(q) : "f"(t));
            v = __byte_perm(v, (unsigned)q, 0x4321);
        }
        w1p[i] = (int)v;
    }
    // ---- quantize + pack W2 (10x16) ----
    if (tid < 40) {
        const int j = tid >> 2, c = tid & 3;
        unsigned v = 0;
#pragma unroll
        for (int b = 0; b < 4; ++b) {
            float t = W2[j * 16 + c * 4 + b] * inv_wa2;
            int q;
            asm("cvt.rni.sat.s8.f32 %0, %1;" : "=r"(q) : "f"(t));
            v = __byte_perm(v, (unsigned)q, 0x4321);
        }
        w2p[tid] = (int)v;
    }
    // (w1p/w2p ordered for all threads by the first pipeline __syncthreads)

    // ---- pipelined staging + MFL recurrence + fc1 ----
    // per chunk: 256 rows x 16 cols = 1024 float4; 4 per thread.
    // f4 idx i = it*256+tid -> row r = i>>2, quad q = i&3.
    const float4* x4 = reinterpret_cast<const float4*>(x) + (size_t)row0 * (NCOLS / 4);

    float4 pf0, pf1, pf2, pf3;
    {
        const int r0 = tid >> 2, q0 = tid & 3;
        pf0 = x4[(size_t)r0 * 32 + q0];
        pf1 = x4[(size_t)(64 + r0) * 32 + q0];
        pf2 = x4[(size_t)(128 + r0) * 32 + q0];
        pf3 = x4[(size_t)(192 + r0) * 32 + q0];
    }

    float w = 1.0f;
    int acc[16];
#pragma unroll
    for (int j = 0; j < 16; ++j) acc[j] = 0;
    unsigned hp = 0;

#pragma unroll
    for (int c = 0; c < NCHUNK; ++c) {
        float* buf = xs + (c & 1) * BUFSZ;
        const int r0 = tid >> 2, q0 = tid & 3;

        // store prefetched chunk c into its buffer (scalar STS: XPAD=17 unaligned)
        {
            float* d0 = &buf[r0 * XPAD + q0 * 4];
            d0[0] = pf0.x; d0[1] = pf0.y; d0[2] = pf0.z; d0[3] = pf0.w;
            float* d1 = &buf[(64 + r0) * XPAD + q0 * 4];
            d1[0] = pf1.x; d1[1] = pf1.y; d1[2] = pf1.z; d1[3] = pf1.w;
            float* d2 = &buf[(128 + r0) * XPAD + q0 * 4];
            d2[0] = pf2.x; d2[1] = pf2.y; d2[2] = pf2.z; d2[3] = pf2.w;
            float* d3 = &buf[(192 + r0) * XPAD + q0 * 4];
            d3[0] = pf3.x; d3[1] = pf3.y; d3[2] = pf3.z; d3[3] = pf3.w;
        }

        // issue LDGs for chunk c+1 BEFORE the barrier -> latency hides under compute
        if (c < NCHUNK - 1) {
            const size_t cb = (size_t)(c + 1) * 4 + q0;
            pf0 = x4[(size_t)r0 * 32 + cb];
            pf1 = x4[(size_t)(64 + r0) * 32 + cb];
            pf2 = x4[(size_t)(128 + r0) * 32 + cb];
            pf3 = x4[(size_t)(192 + r0) * 32 + cb];
        }

        __syncthreads();

        // compute 16 recurrence steps + 4 dp4a groups from buf
        const float* xr = &buf[tid * XPAD];
#pragma unroll
        for (int g = 0; g < 4; ++g) {
#pragma unroll
            for (int b = 0; b < 4; ++b) {
                const float xv = xr[g * 4 + b];
                // quantize w_k: clip+round-half-even == cvt.rni.sat.s8
                const float t = w * inv_a1;
                int hq;
                asm("cvt.rni.sat.s8.f32 %0, %1;" : "=r"(hq) : "f"(t));
                hp = __byte_perm(hp, (unsigned)hq, 0x4321);
                // w' = alpha*rcp(w) + (w - beta*x_k); t2 fma overlaps the MUFU
                const float t2 = __fmaf_rn(-beta, xv, w);
                float r;
                asm("rcp.approx.f32 %0, %1;" : "=f"(r) : "f"(w));
                w = __fmaf_rn(alpha, r, t2);
            }
            const int kc = c * 4 + g;
            const int4* wp = reinterpret_cast<const int4*>(&w1p[kc * 16]);
            const int4 w0 = wp[0], w1v = wp[1], w2v = wp[2], w3v = wp[3];
            acc[0]  = __dp4a((int)hp, w0.x,  acc[0]);
            acc[1]  = __dp4a((int)hp, w0.y,  acc[1]);
            acc[2]  = __dp4a((int)hp, w0.z,  acc[2]);
            acc[3]  = __dp4a((int)hp, w0.w,  acc[3]);
            acc[4]  = __dp4a((int)hp, w1v.x, acc[4]);
            acc[5]  = __dp4a((int)hp, w1v.y, acc[5]);
            acc[6]  = __dp4a((int)hp, w1v.z, acc[6]);
            acc[7]  = __dp4a((int)hp, w1v.w, acc[7]);
            acc[8]  = __dp4a((int)hp, w2v.x, acc[8]);
            acc[9]  = __dp4a((int)hp, w2v.y, acc[9]);
            acc[10] = __dp4a((int)hp, w2v.z, acc[10]);
            acc[11] = __dp4a((int)hp, w2v.w, acc[11]);
            acc[12] = __dp4a((int)hp, w3v.x, acc[12]);
            acc[13] = __dp4a((int)hp, w3v.y, acc[13]);
            acc[14] = __dp4a((int)hp, w3v.z, acc[14]);
            acc[15] = __dp4a((int)hp, w3v.w, acc[15]);
        }
    }

    // ---- epilogue: bias, sigmoid, unsigned quant, signed quant, fc2 (dp4a) ----
    const float s1scale = a1 * wa1;
    unsigned sp[4];
    unsigned spacc = 0;
#pragma unroll
    for (int j = 0; j < 16; ++j) {
        const float h = __fmaf_rn((float)acc[j], s1scale, b1[j]);
        const float sg = __fdividef(1.0f, 1.0f + __expf(-h));
        float u = sg * inv_a2;
        u = fminf(fmaxf(u, 0.0f), 255.0f);
        const float s = (float)__float2int_rn(u) * a2;          // post-sigmoid fq
        const float v2 = s * inv_a3;
        int s2q;
        asm("cvt.rni.sat.s8.f32 %0, %1;" : "=r"(s2q) : "f"(v2)); // qAct3 level
        spacc = __byte_perm(spacc, (unsigned)s2q, 0x4321);
        if ((j & 3) == 3) sp[j >> 2] = spacc;
    }

    // after the last chunk's sync, xs[0] is no longer read by anyone -> reuse
    float* outs = xs;
    const float s2scale = a3 * wa2;
#pragma unroll
    for (int j = 0; j < 10; ++j) {
        int o = 0;
        o = __dp4a((int)sp[0], w2p[j * 4 + 0], o);
        o = __dp4a((int)sp[1], w2p[j * 4 + 1], o);
        o = __dp4a((int)sp[2], w2p[j * 4 + 2], o);
        o = __dp4a((int)sp[3], w2p[j * 4 + 3], o);
        outs[tid * 10 + j] = __fmaf_rn((float)o, s2scale, b2[j]);
    }
    __syncthreads();

    // coalesced output store: 2560 contiguous floats per block
    const size_t obase = (size_t)row0 * 10;
#pragma unroll
    for (int t = 0; t < 10; ++t) {
        const int i = t * THREADS + tid;
        out[obase + i] = outs[i];
    }
}

extern "C" void kernel_launch(void* const* d_in, const int* in_sizes, int n_in,
                              void* d_out, int out_size)
{
    const float* x       = (const float*)d_in[0];
    const float* p_alpha = (const float*)d_in[1];
    const float* p_beta  = (const float*)d_in[2];
    const float* p_a1    = (const float*)d_in[3];
    const float* p_a2    = (const float*)d_in[4];
    const float* p_a3    = (const float*)d_in[5];
    const float* W1      = (const float*)d_in[6];
    const float* b1      = (const float*)d_in[7];
    const float* p_wa1   = (const float*)d_in[8];
    const float* W2      = (const float*)d_in[9];
    const float* b2      = (const float*)d_in[10];
    const float* p_wa2   = (const float*)d_in[11];
    float* out = (float*)d_out;

    const int M = in_sizes[0] / NCOLS;     // 262144
    const int blocks = M / THREADS;        // 1024

    net_quant_kernel<<<blocks, THREADS>>>(x, p_alpha, p_beta, p_a1, p_a2, p_a3,
                                          W1, b1, p_wa1, W2, b2, p_wa2, out);
}